// round 3
// baseline (speedup 1.0000x reference)
#include <cuda_runtime.h>
#include <math.h>

#define B_MAX 2048
// IN_N=50 OUT_N=10 KER=10 FEAT=66 HID=256 VLEN=20 VSEQ=31 IF=40 NBLK=12

__device__ float g_h1q [B_MAX * 5  * 256];
__device__ float g_q   [B_MAX * 256];
__device__ float g_h1k [B_MAX * 35 * 256];
__device__ float g_k2  [B_MAX * 31 * 256];
__device__ float g_att [B_MAX * 31];
__device__ float g_ginp[B_MAX * 66 * 40];
__device__ float g_buf0[B_MAX * 66 * 256];
__device__ float g_buf1[B_MAX * 66 * 256];
__device__ float g_w1qT[416 * 256];
__device__ float g_w2qT[1280 * 256];
__device__ float g_w1kT[416 * 256];
__device__ float g_w2kT[1280 * 256];
__device__ float g_dct [400];

__global__ void k_dct() {
    int t = threadIdx.x;
    if (t < 400) {
        int k = t / 20, i = t % 20;
        float w = (k == 0) ? sqrtf(1.0f / 20.0f) : sqrtf(2.0f / 20.0f);
        g_dct[t] = w * cospif((i + 0.5f) * (float)k / 20.0f);
    }
}

// conv1 w (256,66,6) -> WT[(l*66+f)*256+h], rows padded to 416
__global__ void k_tr1(const float* __restrict__ w, float* __restrict__ wt) {
    for (int i = blockIdx.x * blockDim.x + threadIdx.x; i < 416 * 256;
         i += gridDim.x * blockDim.x) {
        int k = i >> 8, h = i & 255;
        if (k < 396) { int l = k / 66, f = k - l * 66; wt[i] = w[h * 396 + f * 6 + l]; }
        else wt[i] = 0.0f;
    }
}
// conv2 w (256,256,5) -> WT[(l*256+c)*256+h]
__global__ void k_tr2(const float* __restrict__ w, float* __restrict__ wt) {
    for (int i = blockIdx.x * blockDim.x + threadIdx.x; i < 1280 * 256;
         i += gridDim.x * blockDim.x) {
        int k = i >> 8, h = i & 255, l = k >> 8, c = k & 255;
        wt[i] = w[h * 1280 + c * 5 + l];
    }
}

// out[b,p,h] = relu(bias[h] + sum_{l,c} In[b,t0+p+l,c]*WT[(l*S+c)*256+h])
template<int S, int SP, int L, int P, int NT>
__global__ __launch_bounds__(256, 1) void k_conv(
    const float* __restrict__ In, int inStride, int t0,
    const float* __restrict__ WT, const float* __restrict__ bias,
    float* __restrict__ Out)
{
    constexpr int K = L * S, ROWS = P + L - 1, PI = (P + 3) / 4;
    constexpr int ISZ = ((ROWS * SP + 3) / 4) * 4;
    extern __shared__ float sm[];
    float* Ins = sm; float* Wt = sm + ISZ; float* bs = Wt + 8192;
    const int t = threadIdx.x, b = blockIdx.x;
    const int mg = t & 3, h0 = (t >> 2) * 4;
    const float* inb = In + (size_t)b * inStride + t0 * S;
    for (int i = t; i < ROWS * S; i += 256) {
        int r = i / S, c = i - r * S; Ins[r * SP + c] = inb[i];
    }
    bs[t] = bias[t];
    float acc[PI][4];
#pragma unroll
    for (int i = 0; i < PI; i++) { acc[i][0]=0; acc[i][1]=0; acc[i][2]=0; acc[i][3]=0; }
    for (int nt = 0; nt < NT; nt++) {
        __syncthreads();
        for (int i = t; i < 8192; i += 256) {
            int k = nt * 32 + (i >> 8);
            Wt[i] = (k < K) ? WT[k * 256 + (i & 255)] : 0.0f;
        }
        __syncthreads();
#pragma unroll 4
        for (int kk = 0; kk < 32; kk++) {
            int kg = nt * 32 + kk;
            int kc = (K % 32) ? min(kg, K - 1) : kg;
            int l = kc / S, c = kc - l * S;
            float4 w4 = *(const float4*)&Wt[kk * 256 + h0];
#pragma unroll
            for (int i = 0; i < PI; i++) {
                int p = mg + 4 * i;
                if (p < P) {
                    float y = Ins[(p + l) * SP + c];
                    acc[i][0] += y * w4.x; acc[i][1] += y * w4.y;
                    acc[i][2] += y * w4.z; acc[i][3] += y * w4.w;
                }
            }
        }
    }
    float4 bv = *(const float4*)&bs[h0];
#pragma unroll
    for (int i = 0; i < PI; i++) {
        int p = mg + 4 * i;
        if (p < P) {
            float4 z;
            z.x = fmaxf(acc[i][0] + bv.x, 0.0f); z.y = fmaxf(acc[i][1] + bv.y, 0.0f);
            z.z = fmaxf(acc[i][2] + bv.z, 0.0f); z.w = fmaxf(acc[i][3] + bv.w, 0.0f);
            *(float4*)&Out[(size_t)b * P * 256 + p * 256 + h0] = z;
        }
    }
}

__global__ void k_att(const float* __restrict__ qv, const float* __restrict__ k2,
                      float* __restrict__ att) {
    int b = blockIdx.x;
    __shared__ float sc[32];
    int t = threadIdx.x, w = t >> 5, lane = t & 31;
    const float* qb = qv + (size_t)b * 256;
    const float* kb = k2 + (size_t)b * 31 * 256;
    for (int s = w; s < 31; s += 8) {
        float v = 0.0f;
        for (int j = lane; j < 256; j += 32) v += qb[j] * kb[s * 256 + j];
#pragma unroll
        for (int o = 16; o; o >>= 1) v += __shfl_down_sync(0xffffffffu, v, o);
        if (!lane) sc[s] = v;
    }
    __syncthreads();
    if (t < 32) {
        float v = (t < 31) ? sc[t] : 0.0f, tot = v;
#pragma unroll
        for (int o = 16; o; o >>= 1) tot += __shfl_xor_sync(0xffffffffu, tot, o);
        if (t < 31) att[(size_t)b * 31 + t] = v / tot;
    }
}

// gcn_inp = concat(padded_query, att_final) with the reference's flat reshape
__global__ void k_gcninp(const float* __restrict__ x, const float* __restrict__ att,
                         float* __restrict__ out) {
    int b = blockIdx.x;
    __shared__ float xs[3300], as[31], ds[400];
    int t = threadIdx.x;   // 264 threads
    for (int i = t; i < 3300; i += 264) xs[i] = x[(size_t)b * 3300 + i];
    for (int i = t; i < 400; i += 264) ds[i] = g_dct[i];
    if (t < 31) as[t] = att[(size_t)b * 31 + t];
    __syncthreads();
    int f2 = t >> 2, mq = t & 3;
    if (f2 < 66) {
        float G[20];
#pragma unroll
        for (int l = 0; l < 20; l++) G[l] = 0.0f;
        for (int s = 0; s < 31; s++) {
            int j = f2 * 31 + s, sj = j / 66, fj = j - sj * 66;
            float a = as[s];
#pragma unroll
            for (int l = 0; l < 20; l++) G[l] += a * xs[(sj + l) * 66 + fj];
        }
        float xp[20];
#pragma unroll
        for (int l = 0; l < 20; l++) xp[l] = xs[((l < 10) ? (40 + l) : 49) * 66 + f2];
        float* ob = out + (size_t)b * 2640 + f2 * 40;
        for (int m = mq * 5; m < mq * 5 + 5; m++) {
            float pq = 0.0f, af = 0.0f;
#pragma unroll
            for (int l = 0; l < 20; l++) {
                float d = ds[l * 20 + m];
                pq += xp[l] * d; af += G[l] * d;
            }
            ob[m] = pq; ob[20 + m] = af;
        }
    }
}

// fused layer: T=Y@W ; Z=A@T+b ; tanh(bn(Z)) (+res)
template<int KD, bool RES>
__global__ __launch_bounds__(256, 1) void k_layer(
    const float* __restrict__ Yin, const float* __restrict__ W,
    const float* __restrict__ A, const float* __restrict__ bias,
    const float* __restrict__ g, const float* __restrict__ be,
    const float* __restrict__ Res, float* __restrict__ Out)
{
    constexpr int KT = (KD + 31) / 32, YSP = KD + 1;
    constexpr int YSZ = ((66 * YSP + 3) / 4) * 4;
    extern __shared__ float sm[];
    float* Ys = sm; float* Tm = sm + YSZ; float* Wt = Tm + 17424;
    float* As = Wt + 8192; float* bs = As + 4356;
    const int t = threadIdx.x, b = blockIdx.x;
    const int mg = t & 3, h0 = (t >> 2) * 4;
    for (int i = t; i < 66 * KD; i += 256) {
        int r = i / KD, c = i - r * KD;
        Ys[r * YSP + c] = Yin[(size_t)b * 66 * KD + i];
    }
    for (int i = t; i < 4356; i += 256) As[i] = A[i];
    bs[t] = bias[t];
    float acc[17][4];
#pragma unroll
    for (int i = 0; i < 17; i++) { acc[i][0]=0; acc[i][1]=0; acc[i][2]=0; acc[i][3]=0; }
    for (int kt = 0; kt < KT; kt++) {
        __syncthreads();
        for (int i = t; i < 8192; i += 256) {
            int k = kt * 32 + (i >> 8);
            Wt[i] = (k < KD) ? W[k * 256 + (i & 255)] : 0.0f;
        }
        __syncthreads();
#pragma unroll 4
        for (int kk = 0; kk < 32; kk++) {
            int col = kt * 32 + kk;
            if (KD % 32) col = min(col, KD - 1);
            float4 w4 = *(const float4*)&Wt[kk * 256 + h0];
#pragma unroll
            for (int i = 0; i < 17; i++) {
                int m = mg + 4 * i;
                if (m < 66) {
                    float y = Ys[m * YSP + col];
                    acc[i][0] += y * w4.x; acc[i][1] += y * w4.y;
                    acc[i][2] += y * w4.z; acc[i][3] += y * w4.w;
                }
            }
        }
    }
    __syncthreads();
#pragma unroll
    for (int i = 0; i < 17; i++) {
        int m = mg + 4 * i;
        if (m < 66)
            *(float4*)&Tm[m * 264 + h0] = make_float4(acc[i][0], acc[i][1], acc[i][2], acc[i][3]);
    }
    __syncthreads();
#pragma unroll
    for (int i = 0; i < 17; i++) { acc[i][0]=0; acc[i][1]=0; acc[i][2]=0; acc[i][3]=0; }
    for (int m = 0; m < 66; m++) {
        float4 t4 = *(const float4*)&Tm[m * 264 + h0];
#pragma unroll
        for (int i = 0; i < 17; i++) {
            int n = mg + 4 * i;
            if (n < 66) {
                float a = As[n * 66 + m];
                acc[i][0] += a * t4.x; acc[i][1] += a * t4.y;
                acc[i][2] += a * t4.z; acc[i][3] += a * t4.w;
            }
        }
    }
    const float inv = 0.99999500003749973f;  // 1/sqrt(1+1e-5)
    float4 bv = *(const float4*)&bs[h0];
#pragma unroll
    for (int i = 0; i < 17; i++) {
        int n = mg + 4 * i;
        if (n < 66) {
            size_t idx = (size_t)b * 16896 + n * 256 + h0;
            float4 gv = *(const float4*)&g[n * 256 + h0];
            float4 bt = *(const float4*)&be[n * 256 + h0];
            float4 z;
            z.x = tanhf((acc[i][0] + bv.x) * inv * gv.x + bt.x);
            z.y = tanhf((acc[i][1] + bv.y) * inv * gv.y + bt.y);
            z.z = tanhf((acc[i][2] + bv.z) * inv * gv.z + bt.z);
            z.w = tanhf((acc[i][3] + bv.w) * inv * gv.w + bt.w);
            if (RES) {
                float4 r4 = *(const float4*)&Res[idx];
                z.x += r4.x; z.y += r4.y; z.z += r4.z; z.w += r4.w;
            }
            *(float4*)&Out[idx] = z;
        }
    }
}

__global__ __launch_bounds__(256, 1) void k_gout(
    const float* __restrict__ Y, const float* __restrict__ Gin,
    const float* __restrict__ gw, const float* __restrict__ gatt,
    const float* __restrict__ gb, float* __restrict__ out)
{
    int b = blockIdx.x;
    extern __shared__ float sm[];
    float* Ys = sm;            // 66*257 -> 16964
    float* gws = Ys + 16964;   // 256*20
    float* As = gws + 5120;    // 4356
    float* T2 = As + 4356;     // 1320
    float* Z2 = T2 + 1320;     // 1320
    float* ds = Z2 + 1320;     // 400
    float* bsm = ds + 400;     // 20
    int t = threadIdx.x;
    for (int i = t; i < 16896; i += 256) {
        int r = i >> 8, c = i & 255;
        Ys[r * 257 + c] = Y[(size_t)b * 16896 + i];
    }
    for (int i = t; i < 5120; i += 256) {
        int k = i / 20, l = i - k * 20;
        gws[i] = gw[k * 40 + l];
    }
    for (int i = t; i < 4356; i += 256) As[i] = gatt[i];
    for (int i = t; i < 400; i += 256) ds[i] = g_dct[i];
    if (t < 20) bsm[t] = gb[t];
    __syncthreads();
    for (int i = t; i < 1320; i += 256) {
        int m = i / 20, l = i - m * 20;
        float a = 0.0f;
        for (int k = 0; k < 256; k++) a += Ys[m * 257 + k] * gws[k * 20 + l];
        T2[i] = a;
    }
    __syncthreads();
    for (int i = t; i < 1320; i += 256) {
        int n = i / 20, l = i - n * 20;
        float a = bsm[l];
        for (int m = 0; m < 66; m++) a += As[n * 66 + m] * T2[m * 20 + l];
        Z2[i] = a + Gin[(size_t)b * 2640 + n * 40 + l];
    }
    __syncthreads();
    for (int i = t; i < 1320; i += 256) {
        int n = i / 20, m = i - n * 20;
        float a = 0.0f;
#pragma unroll
        for (int l = 0; l < 20; l++) a += Z2[n * 20 + l] * ds[m * 20 + l];  // idct=dct^T
        out[(size_t)b * 1320 + i] = a;
    }
}

extern "C" void kernel_launch(void* const* d_in, const int* in_sizes, int n_in,
                              void* d_out, int out_size)
{
    const float* x        = (const float*)d_in[0];
    const float* q_w1     = (const float*)d_in[1];
    const float* q_b1     = (const float*)d_in[2];
    const float* q_w2     = (const float*)d_in[3];
    const float* q_b2     = (const float*)d_in[4];
    const float* k_w1     = (const float*)d_in[5];
    const float* k_b1     = (const float*)d_in[6];
    const float* k_w2     = (const float*)d_in[7];
    const float* k_b2     = (const float*)d_in[8];
    const float* gin_w    = (const float*)d_in[9];
    const float* gin_att  = (const float*)d_in[10];
    const float* gin_b    = (const float*)d_in[11];
    const float* bn_in_g  = (const float*)d_in[12];
    const float* bn_in_b  = (const float*)d_in[13];
    const float* blk_w    = (const float*)d_in[14];
    const float* blk_att  = (const float*)d_in[15];
    const float* blk_b    = (const float*)d_in[16];
    const float* blk_bn_g = (const float*)d_in[17];
    const float* blk_bn_b = (const float*)d_in[18];
    const float* gout_w   = (const float*)d_in[19];
    const float* gout_att = (const float*)d_in[20];
    const float* gout_b   = (const float*)d_in[21];
    float* out = (float*)d_out;

    int B = in_sizes[0] / 3300;
    if (B > B_MAX) B = B_MAX;
    if (B <= 0) return;

    float *h1q, *qv, *h1k, *k2, *att, *ginp, *b0, *b1, *w1q, *w2q, *w1k, *w2k;
    cudaGetSymbolAddress((void**)&h1q, g_h1q);
    cudaGetSymbolAddress((void**)&qv,  g_q);
    cudaGetSymbolAddress((void**)&h1k, g_h1k);
    cudaGetSymbolAddress((void**)&k2,  g_k2);
    cudaGetSymbolAddress((void**)&att, g_att);
    cudaGetSymbolAddress((void**)&ginp,g_ginp);
    cudaGetSymbolAddress((void**)&b0,  g_buf0);
    cudaGetSymbolAddress((void**)&b1,  g_buf1);
    cudaGetSymbolAddress((void**)&w1q, g_w1qT);
    cudaGetSymbolAddress((void**)&w2q, g_w2qT);
    cudaGetSymbolAddress((void**)&w1k, g_w1kT);
    cudaGetSymbolAddress((void**)&w2k, g_w2kT);

    const int SM_Q1 = 36560, SM_K1 = 44832, SM_Q2 = 39024, SM_K2 = 70336;
    const int SM_L256 = 188768, SM_L40 = 131744, SM_GOUT = 118000;

    cudaFuncSetAttribute((const void*)k_conv<256,261,5,31,40>,
                         cudaFuncAttributeMaxDynamicSharedMemorySize, SM_K2);
    cudaFuncSetAttribute((const void*)k_layer<256,false>,
                         cudaFuncAttributeMaxDynamicSharedMemorySize, SM_L256);
    cudaFuncSetAttribute((const void*)k_layer<256,true>,
                         cudaFuncAttributeMaxDynamicSharedMemorySize, SM_L256);
    cudaFuncSetAttribute((const void*)k_layer<40,false>,
                         cudaFuncAttributeMaxDynamicSharedMemorySize, SM_L40);
    cudaFuncSetAttribute((const void*)k_gout,
                         cudaFuncAttributeMaxDynamicSharedMemorySize, SM_GOUT);

    k_dct<<<1, 400>>>();
    k_tr1<<<128, 256>>>(q_w1, w1q);
    k_tr1<<<128, 256>>>(k_w1, w1k);
    k_tr2<<<256, 256>>>(q_w2, w2q);
    k_tr2<<<256, 256>>>(k_w2, w2k);

    // q: rows 40..49 -> (B,5,256) -> (B,1,256)
    k_conv<66,69,6,5,13><<<B, 256, SM_Q1>>>(x, 3300, 40, w1q, q_b1, h1q);
    k_conv<256,261,5,1,40><<<B, 256, SM_Q2>>>(h1q, 1280, 0, w2q, q_b2, qv);
    // k: rows 0..39 -> (B,35,256) -> (B,31,256)
    k_conv<66,69,6,35,13><<<B, 256, SM_K1>>>(x, 3300, 0, w1k, k_b1, h1k);
    k_conv<256,261,5,31,40><<<B, 256, SM_K2>>>(h1k, 35*256, 0, w2k, k_b2, k2);

    k_att<<<B, 256>>>(qv, k2, att);
    k_gcninp<<<B, 264>>>(x, att, ginp);

    k_layer<40,false><<<B, 256, SM_L40>>>(ginp, gin_w, gin_att, gin_b,
                                          bn_in_g, bn_in_b, nullptr, b0);
    for (int i = 0; i < 12; i += 2) {
        k_layer<256,false><<<B, 256, SM_L256>>>(
            b0, blk_w + (size_t)i * 65536, blk_att + (size_t)i * 4356,
            blk_b + (size_t)i * 256, blk_bn_g + (size_t)i * 16896,
            blk_bn_b + (size_t)i * 16896, nullptr, b1);
        k_layer<256,true><<<B, 256, SM_L256>>>(
            b1, blk_w + (size_t)(i + 1) * 65536, blk_att + (size_t)(i + 1) * 4356,
            blk_b + (size_t)(i + 1) * 256, blk_bn_g + (size_t)(i + 1) * 16896,
            blk_bn_b + (size_t)(i + 1) * 16896, b0, b0);
    }
    k_gout<<<B, 256, SM_GOUT>>>(b0, ginp, gout_w, gout_att, gout_b, out);
}

// round 4
// speedup vs baseline: 1.2863x; 1.2863x over previous
#include <cuda_runtime.h>
#include <math.h>

#define B_MAX 2048
// IN_N=50 OUT_N=10 KER=10 FEAT=66 HID=256 VLEN=20 VSEQ=31 IF=40 NBLK=12

__device__ float g_h1q [B_MAX * 5  * 256];
__device__ float g_q   [B_MAX * 256];
__device__ float g_h1k [B_MAX * 35 * 256];
__device__ float g_k2  [B_MAX * 31 * 256];
__device__ float g_att [B_MAX * 31];
__device__ float g_ginp[B_MAX * 66 * 40];
__device__ float g_buf0[B_MAX * 66 * 256];
__device__ float g_buf1[B_MAX * 66 * 256];
__device__ float g_w1qT[416 * 256];
__device__ float g_w2qT[1280 * 256];
__device__ float g_w1kT[416 * 256];
__device__ float g_w2kT[1280 * 256];
__device__ float g_dct [400];

// ---- packed f32x2 helpers (SASS FFMA2) ----
__device__ __forceinline__ void fma2(unsigned long long& c, unsigned long long a,
                                     unsigned long long b) {
    asm("fma.rn.f32x2 %0, %1, %2, %0;" : "+l"(c) : "l"(a), "l"(b));
}
__device__ __forceinline__ unsigned long long pack2(float x, float y) {
    unsigned long long r;
    asm("mov.b64 %0, {%1, %2};" : "=l"(r) : "f"(x), "f"(y));
    return r;
}
__device__ __forceinline__ float2 unpack2(unsigned long long v) {
    float2 r;
    asm("mov.b64 {%0, %1}, %2;" : "=f"(r.x), "=f"(r.y) : "l"(v));
    return r;
}

__global__ void k_dct() {
    int t = threadIdx.x;
    if (t < 400) {
        int k = t / 20, i = t % 20;
        float w = (k == 0) ? sqrtf(1.0f / 20.0f) : sqrtf(2.0f / 20.0f);
        g_dct[t] = w * cospif((i + 0.5f) * (float)k / 20.0f);
    }
}

__global__ void k_tr1(const float* __restrict__ w, float* __restrict__ wt) {
    for (int i = blockIdx.x * blockDim.x + threadIdx.x; i < 416 * 256;
         i += gridDim.x * blockDim.x) {
        int k = i >> 8, h = i & 255;
        if (k < 396) { int l = k / 66, f = k - l * 66; wt[i] = w[h * 396 + f * 6 + l]; }
        else wt[i] = 0.0f;
    }
}
__global__ void k_tr2(const float* __restrict__ w, float* __restrict__ wt) {
    for (int i = blockIdx.x * blockDim.x + threadIdx.x; i < 1280 * 256;
         i += gridDim.x * blockDim.x) {
        int k = i >> 8, h = i & 255, l = k >> 8, c = k & 255;
        wt[i] = w[h * 1280 + c * 5 + l];
    }
}

// out[b,p,h] = relu(bias[h] + sum_{l,c} In[b,t0+p+l,c]*WT[(l*S+c)*256+h])
template<int S, int SP, int L, int P, int NT>
__global__ __launch_bounds__(256, 2) void k_conv(
    const float* __restrict__ In, int inStride, int t0,
    const float* __restrict__ WT, const float* __restrict__ bias,
    float* __restrict__ Out)
{
    constexpr int K = L * S, ROWS = P + L - 1, PI = (P + 3) / 4;
    constexpr int ISZ = ((ROWS * SP + 3) / 4) * 4;
    extern __shared__ float sm[];
    float* Ins = sm; float* Wt = sm + ISZ; float* bs = Wt + 8192;
    const int t = threadIdx.x, b = blockIdx.x;
    const int mg = t & 3, h0 = (t >> 2) * 4;
    const float* inb = In + (size_t)b * inStride + t0 * S;
    for (int i = t; i < ROWS * S; i += 256) {
        int r = i / S, c = i - r * S; Ins[r * SP + c] = inb[i];
    }
    bs[t] = bias[t];
    unsigned long long acc[PI][2];
#pragma unroll
    for (int i = 0; i < PI; i++) { acc[i][0] = 0ULL; acc[i][1] = 0ULL; }
    for (int nt = 0; nt < NT; nt++) {
        __syncthreads();
        for (int i = t; i < 8192; i += 256) {
            int k = nt * 32 + (i >> 8);
            Wt[i] = (k < K) ? WT[k * 256 + (i & 255)] : 0.0f;
        }
        __syncthreads();
#pragma unroll 4
        for (int kk = 0; kk < 32; kk++) {
            int kg = nt * 32 + kk;
            int kc = (K % 32) ? min(kg, K - 1) : kg;
            int l = kc / S, c = kc - l * S;
            float4 w4 = *(const float4*)&Wt[kk * 256 + h0];
            unsigned long long wlo = pack2(w4.x, w4.y), whi = pack2(w4.z, w4.w);
#pragma unroll
            for (int i = 0; i < PI; i++) {
                int p = mg + 4 * i;
                if (p < P) {
                    float y = Ins[(p + l) * SP + c];
                    unsigned long long yy = pack2(y, y);
                    fma2(acc[i][0], yy, wlo);
                    fma2(acc[i][1], yy, whi);
                }
            }
        }
    }
    float4 bv = *(const float4*)&bs[h0];
#pragma unroll
    for (int i = 0; i < PI; i++) {
        int p = mg + 4 * i;
        if (p < P) {
            float2 lo = unpack2(acc[i][0]), hi = unpack2(acc[i][1]);
            float4 z;
            z.x = fmaxf(lo.x + bv.x, 0.0f); z.y = fmaxf(lo.y + bv.y, 0.0f);
            z.z = fmaxf(hi.x + bv.z, 0.0f); z.w = fmaxf(hi.y + bv.w, 0.0f);
            *(float4*)&Out[(size_t)b * P * 256 + p * 256 + h0] = z;
        }
    }
}

__global__ void k_att(const float* __restrict__ qv, const float* __restrict__ k2,
                      float* __restrict__ att) {
    int b = blockIdx.x;
    __shared__ float sc[32];
    int t = threadIdx.x, w = t >> 5, lane = t & 31;
    const float* qb = qv + (size_t)b * 256;
    const float* kb = k2 + (size_t)b * 31 * 256;
    for (int s = w; s < 31; s += 8) {
        float v = 0.0f;
        for (int j = lane; j < 256; j += 32) v += qb[j] * kb[s * 256 + j];
#pragma unroll
        for (int o = 16; o; o >>= 1) v += __shfl_down_sync(0xffffffffu, v, o);
        if (!lane) sc[s] = v;
    }
    __syncthreads();
    if (t < 32) {
        float v = (t < 31) ? sc[t] : 0.0f, tot = v;
#pragma unroll
        for (int o = 16; o; o >>= 1) tot += __shfl_xor_sync(0xffffffffu, tot, o);
        if (t < 31) att[(size_t)b * 31 + t] = v / tot;
    }
}

__global__ void k_gcninp(const float* __restrict__ x, const float* __restrict__ att,
                         float* __restrict__ out) {
    int b = blockIdx.x;
    __shared__ float xs[3300], as[31], ds[400];
    int t = threadIdx.x;   // 264 threads
    for (int i = t; i < 3300; i += 264) xs[i] = x[(size_t)b * 3300 + i];
    for (int i = t; i < 400; i += 264) ds[i] = g_dct[i];
    if (t < 31) as[t] = att[(size_t)b * 31 + t];
    __syncthreads();
    int f2 = t >> 2, mq = t & 3;
    if (f2 < 66) {
        float G[20];
#pragma unroll
        for (int l = 0; l < 20; l++) G[l] = 0.0f;
        for (int s = 0; s < 31; s++) {
            int j = f2 * 31 + s, sj = j / 66, fj = j - sj * 66;
            float a = as[s];
#pragma unroll
            for (int l = 0; l < 20; l++) G[l] += a * xs[(sj + l) * 66 + fj];
        }
        float xp[20];
#pragma unroll
        for (int l = 0; l < 20; l++) xp[l] = xs[((l < 10) ? (40 + l) : 49) * 66 + f2];
        float* ob = out + (size_t)b * 2640 + f2 * 40;
        for (int m = mq * 5; m < mq * 5 + 5; m++) {
            float pq = 0.0f, af = 0.0f;
#pragma unroll
            for (int l = 0; l < 20; l++) {
                float d = ds[l * 20 + m];
                pq += xp[l] * d; af += G[l] * d;
            }
            ob[m] = pq; ob[20 + m] = af;
        }
    }
}

// fused layer: T=Y@W ; Z=A@T+b ; tanh(bn(Z)) (+res).  Tm aliases Ys (sync-separated).
template<int KD, bool RES>
__global__ __launch_bounds__(256, 2) void k_layer(
    const float* __restrict__ Yin, const float* __restrict__ W,
    const float* __restrict__ A, const float* __restrict__ bias,
    const float* __restrict__ g, const float* __restrict__ be,
    const float* __restrict__ Res, float* __restrict__ Out)
{
    constexpr int KT = (KD + 15) / 16, YSP = KD + 1;
    extern __shared__ float sm[];
    float* Ys = sm;                 // 66*YSP (max 16962)
    float* Tm = sm;                 // 66*264 = 17424 (ALIAS: valid, sync-separated)
    float* Wt = sm + 17424;         // 16*256 = 4096
    float* As = Wt + 4096;          // 4356
    float* bs = As + 4356;          // 256   -> total 26132 floats = 104528 B
    const int t = threadIdx.x, b = blockIdx.x;
    const int mg = t & 3, h0 = (t >> 2) * 4;
    for (int i = t; i < 66 * KD; i += 256) {
        int r = i / KD, c = i - r * KD;
        Ys[r * YSP + c] = Yin[(size_t)b * 66 * KD + i];
    }
    for (int i = t; i < 4356; i += 256) As[i] = A[i];
    bs[t] = bias[t];
    unsigned long long acc[17][2];
#pragma unroll
    for (int i = 0; i < 17; i++) { acc[i][0] = 0ULL; acc[i][1] = 0ULL; }
    for (int kt = 0; kt < KT; kt++) {
        __syncthreads();
        for (int i = t; i < 4096; i += 256) {
            int k = kt * 16 + (i >> 8);
            Wt[i] = (k < KD) ? W[k * 256 + (i & 255)] : 0.0f;
        }
        __syncthreads();
#pragma unroll 4
        for (int kk = 0; kk < 16; kk++) {
            int col = kt * 16 + kk;
            if (KD % 16) col = min(col, KD - 1);
            float4 w4 = *(const float4*)&Wt[kk * 256 + h0];
            unsigned long long wlo = pack2(w4.x, w4.y), whi = pack2(w4.z, w4.w);
#pragma unroll
            for (int i = 0; i < 17; i++) {
                int m = mg + 4 * i;
                if (m < 66) {
                    float y = Ys[m * YSP + col];
                    unsigned long long yy = pack2(y, y);
                    fma2(acc[i][0], yy, wlo);
                    fma2(acc[i][1], yy, whi);
                }
            }
        }
    }
    __syncthreads();   // last Ys read done -> Tm may overwrite
#pragma unroll
    for (int i = 0; i < 17; i++) {
        int m = mg + 4 * i;
        if (m < 66) {
            float2 lo = unpack2(acc[i][0]), hi = unpack2(acc[i][1]);
            *(float4*)&Tm[m * 264 + h0] = make_float4(lo.x, lo.y, hi.x, hi.y);
        }
    }
    __syncthreads();
#pragma unroll
    for (int i = 0; i < 17; i++) { acc[i][0] = 0ULL; acc[i][1] = 0ULL; }
    for (int m = 0; m < 66; m++) {
        float4 t4 = *(const float4*)&Tm[m * 264 + h0];
        unsigned long long tlo = pack2(t4.x, t4.y), thi = pack2(t4.z, t4.w);
#pragma unroll
        for (int i = 0; i < 17; i++) {
            int n = mg + 4 * i;
            if (n < 66) {
                float a = As[n * 66 + m];
                unsigned long long aa = pack2(a, a);
                fma2(acc[i][0], aa, tlo);
                fma2(acc[i][1], aa, thi);
            }
        }
    }
    const float inv = 0.99999500003749973f;  // 1/sqrt(1+1e-5)
    float4 bv = *(const float4*)&bs[h0];
#pragma unroll
    for (int i = 0; i < 17; i++) {
        int n = mg + 4 * i;
        if (n < 66) {
            size_t idx = (size_t)b * 16896 + n * 256 + h0;
            float4 gv = *(const float4*)&g[n * 256 + h0];
            float4 bt = *(const float4*)&be[n * 256 + h0];
            float2 lo = unpack2(acc[i][0]), hi = unpack2(acc[i][1]);
            float4 z;
            z.x = tanhf((lo.x + bv.x) * inv * gv.x + bt.x);
            z.y = tanhf((lo.y + bv.y) * inv * gv.y + bt.y);
            z.z = tanhf((hi.x + bv.z) * inv * gv.z + bt.z);
            z.w = tanhf((hi.y + bv.w) * inv * gv.w + bt.w);
            if (RES) {
                float4 r4 = *(const float4*)&Res[idx];
                z.x += r4.x; z.y += r4.y; z.z += r4.z; z.w += r4.w;
            }
            *(float4*)&Out[idx] = z;
        }
    }
}

__global__ __launch_bounds__(256, 1) void k_gout(
    const float* __restrict__ Y, const float* __restrict__ Gin,
    const float* __restrict__ gw, const float* __restrict__ gatt,
    const float* __restrict__ gb, float* __restrict__ out)
{
    int b = blockIdx.x;
    extern __shared__ float sm[];
    float* Ys = sm;            // 66*257 -> 16964
    float* gws = Ys + 16964;   // 5120
    float* As = gws + 5120;    // 4356
    float* T2 = As + 4356;     // 1320
    float* Z2 = T2 + 1320;     // 1320
    float* ds = Z2 + 1320;     // 400
    float* bsm = ds + 400;     // 20
    int t = threadIdx.x;
    for (int i = t; i < 16896; i += 256) {
        int r = i >> 8, c = i & 255;
        Ys[r * 257 + c] = Y[(size_t)b * 16896 + i];
    }
    for (int i = t; i < 5120; i += 256) {
        int k = i / 20, l = i - k * 20;
        gws[i] = gw[k * 40 + l];
    }
    for (int i = t; i < 4356; i += 256) As[i] = gatt[i];
    for (int i = t; i < 400; i += 256) ds[i] = g_dct[i];
    if (t < 20) bsm[t] = gb[t];
    __syncthreads();
    for (int i = t; i < 1320; i += 256) {
        int m = i / 20, l = i - m * 20;
        float a = 0.0f;
        for (int k = 0; k < 256; k++) a += Ys[m * 257 + k] * gws[k * 20 + l];
        T2[i] = a;
    }
    __syncthreads();
    for (int i = t; i < 1320; i += 256) {
        int n = i / 20, l = i - n * 20;
        float a = bsm[l];
        for (int m = 0; m < 66; m++) a += As[n * 66 + m] * T2[m * 20 + l];
        Z2[i] = a + Gin[(size_t)b * 2640 + n * 40 + l];
    }
    __syncthreads();
    for (int i = t; i < 1320; i += 256) {
        int n = i / 20, m = i - n * 20;
        float a = 0.0f;
#pragma unroll
        for (int l = 0; l < 20; l++) a += Z2[n * 20 + l] * ds[m * 20 + l];  // idct=dct^T
        out[(size_t)b * 1320 + i] = a;
    }
}

extern "C" void kernel_launch(void* const* d_in, const int* in_sizes, int n_in,
                              void* d_out, int out_size)
{
    const float* x        = (const float*)d_in[0];
    const float* q_w1     = (const float*)d_in[1];
    const float* q_b1     = (const float*)d_in[2];
    const float* q_w2     = (const float*)d_in[3];
    const float* q_b2     = (const float*)d_in[4];
    const float* k_w1     = (const float*)d_in[5];
    const float* k_b1     = (const float*)d_in[6];
    const float* k_w2     = (const float*)d_in[7];
    const float* k_b2     = (const float*)d_in[8];
    const float* gin_w    = (const float*)d_in[9];
    const float* gin_att  = (const float*)d_in[10];
    const float* gin_b    = (const float*)d_in[11];
    const float* bn_in_g  = (const float*)d_in[12];
    const float* bn_in_b  = (const float*)d_in[13];
    const float* blk_w    = (const float*)d_in[14];
    const float* blk_att  = (const float*)d_in[15];
    const float* blk_b    = (const float*)d_in[16];
    const float* blk_bn_g = (const float*)d_in[17];
    const float* blk_bn_b = (const float*)d_in[18];
    const float* gout_w   = (const float*)d_in[19];
    const float* gout_att = (const float*)d_in[20];
    const float* gout_b   = (const float*)d_in[21];
    float* out = (float*)d_out;

    int B = in_sizes[0] / 3300;
    if (B > B_MAX) B = B_MAX;
    if (B <= 0) return;

    float *h1q, *qv, *h1k, *k2, *att, *ginp, *b0, *b1, *w1q, *w2q, *w1k, *w2k;
    cudaGetSymbolAddress((void**)&h1q, g_h1q);
    cudaGetSymbolAddress((void**)&qv,  g_q);
    cudaGetSymbolAddress((void**)&h1k, g_h1k);
    cudaGetSymbolAddress((void**)&k2,  g_k2);
    cudaGetSymbolAddress((void**)&att, g_att);
    cudaGetSymbolAddress((void**)&ginp,g_ginp);
    cudaGetSymbolAddress((void**)&b0,  g_buf0);
    cudaGetSymbolAddress((void**)&b1,  g_buf1);
    cudaGetSymbolAddress((void**)&w1q, g_w1qT);
    cudaGetSymbolAddress((void**)&w2q, g_w2qT);
    cudaGetSymbolAddress((void**)&w1k, g_w1kT);
    cudaGetSymbolAddress((void**)&w2k, g_w2kT);

    const int SM_Q1 = 36560, SM_K1 = 44832, SM_Q2 = 39024, SM_K2 = 70336;
    const int SM_L = 104528, SM_GOUT = 118000;

    cudaFuncSetAttribute((const void*)k_conv<256,261,5,31,40>,
                         cudaFuncAttributeMaxDynamicSharedMemorySize, SM_K2);
    cudaFuncSetAttribute((const void*)k_layer<256,false>,
                         cudaFuncAttributeMaxDynamicSharedMemorySize, SM_L);
    cudaFuncSetAttribute((const void*)k_layer<256,true>,
                         cudaFuncAttributeMaxDynamicSharedMemorySize, SM_L);
    cudaFuncSetAttribute((const void*)k_layer<40,false>,
                         cudaFuncAttributeMaxDynamicSharedMemorySize, SM_L);
    cudaFuncSetAttribute((const void*)k_gout,
                         cudaFuncAttributeMaxDynamicSharedMemorySize, SM_GOUT);

    k_dct<<<1, 400>>>();
    k_tr1<<<128, 256>>>(q_w1, w1q);
    k_tr1<<<128, 256>>>(k_w1, w1k);
    k_tr2<<<256, 256>>>(q_w2, w2q);
    k_tr2<<<256, 256>>>(k_w2, w2k);

    // q: rows 40..49 -> (B,5,256) -> (B,1,256)
    k_conv<66,69,6,5,13><<<B, 256, SM_Q1>>>(x, 3300, 40, w1q, q_b1, h1q);
    k_conv<256,261,5,1,40><<<B, 256, SM_Q2>>>(h1q, 1280, 0, w2q, q_b2, qv);
    // k: rows 0..39 -> (B,35,256) -> (B,31,256)
    k_conv<66,69,6,35,13><<<B, 256, SM_K1>>>(x, 3300, 0, w1k, k_b1, h1k);
    k_conv<256,261,5,31,40><<<B, 256, SM_K2>>>(h1k, 35*256, 0, w2k, k_b2, k2);

    k_att<<<B, 256>>>(qv, k2, att);
    k_gcninp<<<B, 264>>>(x, att, ginp);

    k_layer<40,false><<<B, 256, SM_L>>>(ginp, gin_w, gin_att, gin_b,
                                        bn_in_g, bn_in_b, nullptr, b0);
    for (int i = 0; i < 12; i += 2) {
        k_layer<256,false><<<B, 256, SM_L>>>(
            b0, blk_w + (size_t)i * 65536, blk_att + (size_t)i * 4356,
            blk_b + (size_t)i * 256, blk_bn_g + (size_t)i * 16896,
            blk_bn_b + (size_t)i * 16896, nullptr, b1);
        k_layer<256,true><<<B, 256, SM_L>>>(
            b1, blk_w + (size_t)(i + 1) * 65536, blk_att + (size_t)(i + 1) * 4356,
            blk_b + (size_t)(i + 1) * 256, blk_bn_g + (size_t)(i + 1) * 16896,
            blk_bn_b + (size_t)(i + 1) * 16896, b0, b0);
    }
    k_gout<<<B, 256, SM_GOUT>>>(b0, ginp, gout_w, gout_att, gout_b, out);
}

// round 9
// speedup vs baseline: 1.4288x; 1.1107x over previous
#include <cuda_runtime.h>
#include <cuda_bf16.h>
#include <math.h>
#include <stdint.h>

#define B_MAX 2048
// IN_N=50 OUT_N=10 KER=10 FEAT=66 HID=256 VLEN=20 VSEQ=31 IF=40 NBLK=12

__device__ float g_h1q [B_MAX * 5  * 256];
__device__ float g_q   [B_MAX * 256];
__device__ float g_h1k [B_MAX * 35 * 256];
__device__ float g_k2  [B_MAX * 31 * 256];
__device__ float g_att [B_MAX * 31];
__device__ float g_ginp[B_MAX * 66 * 40];
__device__ float g_buf0[B_MAX * 66 * 256];
__device__ float g_buf1[B_MAX * 66 * 256];
__device__ float g_w1qT[416 * 256];
__device__ float g_w2qT[1280 * 256];
__device__ float g_w1kT[416 * 256];
__device__ float g_w2kT[1280 * 256];
__device__ float g_dct [400];
__device__ __nv_bfloat16 g_whi[13 * 65536];
__device__ __nv_bfloat16 g_wlo[13 * 65536];

// ---- packed f32x2 helpers (SASS FFMA2) ----
__device__ __forceinline__ void fma2(unsigned long long& c, unsigned long long a,
                                     unsigned long long b) {
    asm("fma.rn.f32x2 %0, %1, %2, %0;" : "+l"(c) : "l"(a), "l"(b));
}
__device__ __forceinline__ unsigned long long pack2(float x, float y) {
    unsigned long long r;
    asm("mov.b64 %0, {%1, %2};" : "=l"(r) : "f"(x), "f"(y));
    return r;
}
__device__ __forceinline__ float2 unpack2(unsigned long long v) {
    float2 r;
    asm("mov.b64 {%0, %1}, %2;" : "=f"(r.x), "=f"(r.y) : "l"(v));
    return r;
}

// ---- mma.sync helpers (sm_80 baseline PTX -> legacy HMMA pipe) ----
__device__ __forceinline__ uint32_t smem_u32(const void* p) {
    uint32_t a;
    asm("{ .reg .u64 t; cvta.to.shared.u64 t, %1; cvt.u32.u64 %0, t; }"
        : "=r"(a) : "l"(p));
    return a;
}
__device__ __forceinline__ void ldsm4(uint32_t* r, uint32_t addr) {
    asm volatile("ldmatrix.sync.aligned.m8n8.x4.shared.b16 {%0,%1,%2,%3}, [%4];"
                 : "=r"(r[0]), "=r"(r[1]), "=r"(r[2]), "=r"(r[3]) : "r"(addr));
}
__device__ __forceinline__ void mma16816(float* d, const uint32_t* a, const uint32_t* b) {
    asm volatile(
        "mma.sync.aligned.m16n8k16.row.col.f32.bf16.bf16.f32 "
        "{%0,%1,%2,%3}, {%4,%5,%6,%7}, {%8,%9}, {%0,%1,%2,%3};"
        : "+f"(d[0]), "+f"(d[1]), "+f"(d[2]), "+f"(d[3])
        : "r"(a[0]), "r"(a[1]), "r"(a[2]), "r"(a[3]), "r"(b[0]), "r"(b[1]));
}

__global__ void k_dct() {
    int t = threadIdx.x;
    if (t < 400) {
        int k = t / 20, i = t % 20;
        float w = (k == 0) ? sqrtf(1.0f / 20.0f) : sqrtf(2.0f / 20.0f);
        g_dct[t] = w * cospif((i + 0.5f) * (float)k / 20.0f);
    }
}

__global__ void k_tr1(const float* __restrict__ w, float* __restrict__ wt) {
    for (int i = blockIdx.x * blockDim.x + threadIdx.x; i < 416 * 256;
         i += gridDim.x * blockDim.x) {
        int k = i >> 8, h = i & 255;
        if (k < 396) { int l = k / 66, f = k - l * 66; wt[i] = w[h * 396 + f * 6 + l]; }
        else wt[i] = 0.0f;
    }
}
__global__ void k_tr2(const float* __restrict__ w, float* __restrict__ wt) {
    for (int i = blockIdx.x * blockDim.x + threadIdx.x; i < 1280 * 256;
         i += gridDim.x * blockDim.x) {
        int k = i >> 8, h = i & 255, l = k >> 8, c = k & 255;
        wt[i] = w[h * 1280 + c * 5 + l];
    }
}

// split layer weights into bf16 hi/lo, layout [layer][kchunk][n(256)][k(64)]
__global__ void k_wpack(const float* __restrict__ gin_w, const float* __restrict__ blk_w) {
    int idx = blockIdx.x * blockDim.x + threadIdx.x;
    if (idx >= 13 * 65536) return;
    int l = idx >> 16, r = idx & 65535;
    int kc = r >> 14, rem = r & 16383;
    int n = rem >> 6, kk = rem & 63;
    int k = kc * 64 + kk;
    float a;
    if (l == 0) a = (k < 40) ? gin_w[k * 256 + n] : 0.0f;
    else        a = blk_w[(size_t)(l - 1) * 65536 + k * 256 + n];
    __nv_bfloat16 h = __float2bfloat16(a);
    __nv_bfloat16 lo = __float2bfloat16(a - __bfloat162float(h));
    g_whi[idx] = h; g_wlo[idx] = lo;
}

// out[b,p,h] = relu(bias[h] + sum_{l,c} In[b,t0+p+l,c]*WT[(l*S+c)*256+h])
template<int S, int SP, int L, int P, int NT>
__global__ __launch_bounds__(256, 2) void k_conv(
    const float* __restrict__ In, int inStride, int t0,
    const float* __restrict__ WT, const float* __restrict__ bias,
    float* __restrict__ Out)
{
    constexpr int K = L * S, ROWS = P + L - 1, PI = (P + 3) / 4;
    constexpr int ISZ = ((ROWS * SP + 3) / 4) * 4;
    extern __shared__ float sm[];
    float* Ins = sm; float* Wt = sm + ISZ; float* bs = Wt + 8192;
    const int t = threadIdx.x, b = blockIdx.x;
    const int mg = t & 3, h0 = (t >> 2) * 4;
    const float* inb = In + (size_t)b * inStride + t0 * S;
    for (int i = t; i < ROWS * S; i += 256) {
        int r = i / S, c = i - r * S; Ins[r * SP + c] = inb[i];
    }
    bs[t] = bias[t];
    unsigned long long acc[PI][2];
#pragma unroll
    for (int i = 0; i < PI; i++) { acc[i][0] = 0ULL; acc[i][1] = 0ULL; }
    for (int nt = 0; nt < NT; nt++) {
        __syncthreads();
        for (int i = t; i < 8192; i += 256) {
            int k = nt * 32 + (i >> 8);
            Wt[i] = (k < K) ? WT[k * 256 + (i & 255)] : 0.0f;
        }
        __syncthreads();
#pragma unroll 4
        for (int kk = 0; kk < 32; kk++) {
            int kg = nt * 32 + kk;
            int kc = (K % 32) ? min(kg, K - 1) : kg;
            int l = kc / S, c = kc - l * S;
            float4 w4 = *(const float4*)&Wt[kk * 256 + h0];
            unsigned long long wlo = pack2(w4.x, w4.y), whi = pack2(w4.z, w4.w);
#pragma unroll
            for (int i = 0; i < PI; i++) {
                int p = mg + 4 * i;
                if (p < P) {
                    float y = Ins[(p + l) * SP + c];
                    unsigned long long yy = pack2(y, y);
                    fma2(acc[i][0], yy, wlo);
                    fma2(acc[i][1], yy, whi);
                }
            }
        }
    }
    float4 bv = *(const float4*)&bs[h0];
#pragma unroll
    for (int i = 0; i < PI; i++) {
        int p = mg + 4 * i;
        if (p < P) {
            float2 lo = unpack2(acc[i][0]), hi = unpack2(acc[i][1]);
            float4 z;
            z.x = fmaxf(lo.x + bv.x, 0.0f); z.y = fmaxf(lo.y + bv.y, 0.0f);
            z.z = fmaxf(hi.x + bv.z, 0.0f); z.w = fmaxf(hi.y + bv.w, 0.0f);
            *(float4*)&Out[(size_t)b * P * 256 + p * 256 + h0] = z;
        }
    }
}

__global__ void k_att(const float* __restrict__ qv, const float* __restrict__ k2,
                      float* __restrict__ att) {
    int b = blockIdx.x;
    __shared__ float sc[32];
    int t = threadIdx.x, w = t >> 5, lane = t & 31;
    const float* qb = qv + (size_t)b * 256;
    const float* kb = k2 + (size_t)b * 31 * 256;
    for (int s = w; s < 31; s += 8) {
        float v = 0.0f;
        for (int j = lane; j < 256; j += 32) v += qb[j] * kb[s * 256 + j];
#pragma unroll
        for (int o = 16; o; o >>= 1) v += __shfl_down_sync(0xffffffffu, v, o);
        if (!lane) sc[s] = v;
    }
    __syncthreads();
    if (t < 32) {
        float v = (t < 31) ? sc[t] : 0.0f, tot = v;
#pragma unroll
        for (int o = 16; o; o >>= 1) tot += __shfl_xor_sync(0xffffffffu, tot, o);
        if (t < 31) att[(size_t)b * 31 + t] = v / tot;
    }
}

__global__ void k_gcninp(const float* __restrict__ x, const float* __restrict__ att,
                         float* __restrict__ out) {
    int b = blockIdx.x;
    __shared__ float xs[3300], as[31], ds[400];
    int t = threadIdx.x;   // 264 threads
    for (int i = t; i < 3300; i += 264) xs[i] = x[(size_t)b * 3300 + i];
    for (int i = t; i < 400; i += 264) ds[i] = g_dct[i];
    if (t < 31) as[t] = att[(size_t)b * 31 + t];
    __syncthreads();
    int f2 = t >> 2, mq = t & 3;
    if (f2 < 66) {
        float G[20];
#pragma unroll
        for (int l = 0; l < 20; l++) G[l] = 0.0f;
        for (int s = 0; s < 31; s++) {
            int j = f2 * 31 + s, sj = j / 66, fj = j - sj * 66;
            float a = as[s];
#pragma unroll
            for (int l = 0; l < 20; l++) G[l] += a * xs[(sj + l) * 66 + fj];
        }
        float xp[20];
#pragma unroll
        for (int l = 0; l < 20; l++) xp[l] = xs[((l < 10) ? (40 + l) : 49) * 66 + f2];
        float* ob = out + (size_t)b * 2640 + f2 * 40;
        for (int m = mq * 5; m < mq * 5 + 5; m++) {
            float pq = 0.0f, af = 0.0f;
#pragma unroll
            for (int l = 0; l < 20; l++) {
                float d = ds[l * 20 + m];
                pq += xp[l] * d; af += G[l] * d;
            }
            ob[m] = pq; ob[20 + m] = af;
        }
    }
}

// ---- tensor-core (mma.sync) fused layer ----
// GEMM smem bytes: Whi@0 (256x72 bf16 = 36864), Wlo@36864, Ahi@73728 (96x72x2b = 13824),
//                  Alo@87552, bs@101376 (1KB) -> total 102400
// epilogue alias:  Tm floats [0,17424), As floats [17424,21780)  (GEMM region, post-sync)
template<int KD, int NCHUNK, bool RES>
__global__ __launch_bounds__(256, 1) void k_tlayer(
    const float* __restrict__ Yin,
    const __nv_bfloat16* __restrict__ Whi, const __nv_bfloat16* __restrict__ Wlo,
    const float* __restrict__ A, const float* __restrict__ bias,
    const float* __restrict__ g, const float* __restrict__ be,
    const float* __restrict__ Res, float* __restrict__ Out)
{
    extern __shared__ float sm[];
    char* smc = (char*)sm;
    float* Tm = sm;
    float* As = sm + 17424;
    float* bs = (float*)(smc + 101376);
    const int t = threadIdx.x, b = blockIdx.x;
    const int wid = t >> 5, lid = t & 31;
    const int wm = wid >> 2, wn = wid & 3;   // 2 x 4 warp grid
    const uint32_t sA_hi = smem_u32(smc + 73728);
    const uint32_t sA_lo = smem_u32(smc + 87552);
    const uint32_t sB_hi = smem_u32(smc);
    const uint32_t sB_lo = smem_u32(smc + 36864);

    bs[t] = bias[t];
    // zero pad rows 66..95 of Ahi/Alo once (1080 u32 each)
    for (int i = t; i < 1080; i += 256) {
        ((uint32_t*)(smc + 73728 + 66 * 144))[i] = 0;
        ((uint32_t*)(smc + 87552 + 66 * 144))[i] = 0;
    }

    float c[3][8][4];
#pragma unroll
    for (int mi = 0; mi < 3; mi++)
#pragma unroll
        for (int ni = 0; ni < 8; ni++)
#pragma unroll
            for (int j = 0; j < 4; j++) c[mi][ni][j] = 0.0f;

    for (int kc = 0; kc < NCHUNK; kc++) {
        __syncthreads();
        // W chunk copy: [n=256][k=64] bf16 per term -> rows padded to 144B
        {
            const uint4* srcH = (const uint4*)(Whi + kc * 16384);
            const uint4* srcL = (const uint4*)(Wlo + kc * 16384);
            for (int i = t; i < 2048; i += 256) {
                int n = i >> 3, j = i & 7;
                *(uint4*)(smc + n * 144 + j * 16) = srcH[i];
                *(uint4*)(smc + 36864 + n * 144 + j * 16) = srcL[i];
            }
        }
        // Y chunk convert: 66 rows x 64 cols
        for (int i = t; i < 66 * 64; i += 256) {
            int m = i >> 6, j = i & 63, col = kc * 64 + j;
            float a = (col < KD) ? Yin[(size_t)b * 66 * KD + m * KD + col] : 0.0f;
            __nv_bfloat16 h = __float2bfloat16(a);
            __nv_bfloat16 l = __float2bfloat16(a - __bfloat162float(h));
            *(__nv_bfloat16*)(smc + 73728 + m * 144 + j * 2) = h;
            *(__nv_bfloat16*)(smc + 87552 + m * 144 + j * 2) = l;
        }
        __syncthreads();
#pragma unroll
        for (int s = 0; s < 4; s++) {
            uint32_t ah[3][4], al[3][4];
#pragma unroll
            for (int mi = 0; mi < 3; mi++) {
                int R = wm * 48 + mi * 16;
                uint32_t off = (uint32_t)(R + (lid & 7) + ((lid >> 3) & 1) * 8) * 144
                             + s * 32 + ((lid >> 4) & 1) * 16;
                ldsm4(ah[mi], sA_hi + off);
                ldsm4(al[mi], sA_lo + off);
            }
#pragma unroll
            for (int np = 0; np < 4; np++) {
                int Nb = wn * 64 + np * 16;
                uint32_t off = (uint32_t)(Nb + (lid & 7) + ((lid >> 4) & 1) * 8) * 144
                             + s * 32 + ((lid >> 3) & 1) * 16;
                uint32_t bh[4], bl[4];
                ldsm4(bh, sB_hi + off);
                ldsm4(bl, sB_lo + off);
#pragma unroll
                for (int mi = 0; mi < 3; mi++) {
                    mma16816(c[mi][np * 2],     ah[mi], bh);
                    mma16816(c[mi][np * 2 + 1], ah[mi], bh + 2);
                    mma16816(c[mi][np * 2],     ah[mi], bl);
                    mma16816(c[mi][np * 2 + 1], ah[mi], bl + 2);
                    mma16816(c[mi][np * 2],     al[mi], bh);
                    mma16816(c[mi][np * 2 + 1], al[mi], bh + 2);
                }
            }
        }
    }
    __syncthreads();   // all ldmatrix done -> safe to overwrite with Tm/As

    // store accumulators to Tm (rows < 66), load As
#pragma unroll
    for (int mi = 0; mi < 3; mi++) {
        int r0 = wm * 48 + mi * 16 + (lid >> 2);
#pragma unroll
        for (int ni = 0; ni < 8; ni++) {
            int cc = wn * 64 + ni * 8 + (lid & 3) * 2;
            if (r0 < 66)
                *(float2*)&Tm[r0 * 264 + cc] = make_float2(c[mi][ni][0], c[mi][ni][1]);
            if (r0 + 8 < 66)
                *(float2*)&Tm[(r0 + 8) * 264 + cc] = make_float2(c[mi][ni][2], c[mi][ni][3]);
        }
    }
    for (int i = t; i < 4356; i += 256) As[i] = A[i];
    __syncthreads();

    // A-mix + BN + tanh (+res), scalar FFMA2
    const int mg = t & 3, h0 = (t >> 2) * 4;
    unsigned long long acc[17][2];
#pragma unroll
    for (int i = 0; i < 17; i++) { acc[i][0] = 0ULL; acc[i][1] = 0ULL; }
    for (int m = 0; m < 66; m++) {
        float4 t4 = *(const float4*)&Tm[m * 264 + h0];
        unsigned long long tlo = pack2(t4.x, t4.y), thi = pack2(t4.z, t4.w);
#pragma unroll
        for (int i = 0; i < 17; i++) {
            int n = mg + 4 * i;
            if (n < 66) {
                float a = As[n * 66 + m];
                unsigned long long aa = pack2(a, a);
                fma2(acc[i][0], aa, tlo);
                fma2(acc[i][1], aa, thi);
            }
        }
    }
    const float inv = 0.99999500003749973f;  // 1/sqrt(1+1e-5)
    float4 bv = *(const float4*)&bs[h0];
#pragma unroll
    for (int i = 0; i < 17; i++) {
        int n = mg + 4 * i;
        if (n < 66) {
            size_t idx = (size_t)b * 16896 + n * 256 + h0;
            float4 gv = *(const float4*)&g[n * 256 + h0];
            float4 bt = *(const float4*)&be[n * 256 + h0];
            float2 lo = unpack2(acc[i][0]), hi = unpack2(acc[i][1]);
            float4 z;
            z.x = tanhf((lo.x + bv.x) * inv * gv.x + bt.x);
            z.y = tanhf((lo.y + bv.y) * inv * gv.y + bt.y);
            z.z = tanhf((hi.x + bv.z) * inv * gv.z + bt.z);
            z.w = tanhf((hi.y + bv.w) * inv * gv.w + bt.w);
            if (RES) {
                float4 r4 = *(const float4*)&Res[idx];
                z.x += r4.x; z.y += r4.y; z.z += r4.z; z.w += r4.w;
            }
            *(float4*)&Out[idx] = z;
        }
    }
}

__global__ __launch_bounds__(256, 1) void k_gout(
    const float* __restrict__ Y, const float* __restrict__ Gin,
    const float* __restrict__ gw, const float* __restrict__ gatt,
    const float* __restrict__ gb, float* __restrict__ out)
{
    int b = blockIdx.x;
    extern __shared__ float sm[];
    float* Ys = sm;            // 66*257 -> 16964
    float* gws = Ys + 16964;   // 5120
    float* As = gws + 5120;    // 4356
    float* T2 = As + 4356;     // 1320
    float* Z2 = T2 + 1320;     // 1320
    float* ds = Z2 + 1320;     // 400
    float* bsm = ds + 400;     // 20
    int t = threadIdx.x;
    for (int i = t; i < 16896; i += 256) {
        int r = i >> 8, c = i & 255;
        Ys[r * 257 + c] = Y[(size_t)b * 16896 + i];
    }
    for (int i = t; i < 5120; i += 256) {
        int k = i / 20, l = i - k * 20;
        gws[i] = gw[k * 40 + l];
    }
    for (int i = t; i < 4356; i += 256) As[i] = gatt[i];
    for (int i = t; i < 400; i += 256) ds[i] = g_dct[i];
    if (t < 20) bsm[t] = gb[t];
    __syncthreads();
    for (int i = t; i < 1320; i += 256) {
        int m = i / 20, l = i - m * 20;
        float a = 0.0f;
        for (int k = 0; k < 256; k++) a += Ys[m * 257 + k] * gws[k * 20 + l];
        T2[i] = a;
    }
    __syncthreads();
    for (int i = t; i < 1320; i += 256) {
        int n = i / 20, l = i - n * 20;
        float a = bsm[l];
        for (int m = 0; m < 66; m++) a += As[n * 66 + m] * T2[m * 20 + l];
        Z2[i] = a + Gin[(size_t)b * 2640 + n * 40 + l];
    }
    __syncthreads();
    for (int i = t; i < 1320; i += 256) {
        int n = i / 20, m = i - n * 20;
        float a = 0.0f;
#pragma unroll
        for (int l = 0; l < 20; l++) a += Z2[n * 20 + l] * ds[m * 20 + l];  // idct=dct^T
        out[(size_t)b * 1320 + i] = a;
    }
}

extern "C" void kernel_launch(void* const* d_in, const int* in_sizes, int n_in,
                              void* d_out, int out_size)
{
    const float* x        = (const float*)d_in[0];
    const float* q_w1     = (const float*)d_in[1];
    const float* q_b1     = (const float*)d_in[2];
    const float* q_w2     = (const float*)d_in[3];
    const float* q_b2     = (const float*)d_in[4];
    const float* k_w1     = (const float*)d_in[5];
    const float* k_b1     = (const float*)d_in[6];
    const float* k_w2     = (const float*)d_in[7];
    const float* k_b2     = (const float*)d_in[8];
    const float* gin_w    = (const float*)d_in[9];
    const float* gin_att  = (const float*)d_in[10];
    const float* gin_b    = (const float*)d_in[11];
    const float* bn_in_g  = (const float*)d_in[12];
    const float* bn_in_b  = (const float*)d_in[13];
    const float* blk_w    = (const float*)d_in[14];
    const float* blk_att  = (const float*)d_in[15];
    const float* blk_b    = (const float*)d_in[16];
    const float* blk_bn_g = (const float*)d_in[17];
    const float* blk_bn_b = (const float*)d_in[18];
    const float* gout_w   = (const float*)d_in[19];
    const float* gout_att = (const float*)d_in[20];
    const float* gout_b   = (const float*)d_in[21];
    float* out = (float*)d_out;

    int B = in_sizes[0] / 3300;
    if (B > B_MAX) B = B_MAX;
    if (B <= 0) return;

    float *h1q, *qv, *h1k, *k2, *att, *ginp, *b0, *b1, *w1q, *w2q, *w1k, *w2k;
    __nv_bfloat16 *whi, *wlo;
    cudaGetSymbolAddress((void**)&h1q, g_h1q);
    cudaGetSymbolAddress((void**)&qv,  g_q);
    cudaGetSymbolAddress((void**)&h1k, g_h1k);
    cudaGetSymbolAddress((void**)&k2,  g_k2);
    cudaGetSymbolAddress((void**)&att, g_att);
    cudaGetSymbolAddress((void**)&ginp,g_ginp);
    cudaGetSymbolAddress((void**)&b0,  g_buf0);
    cudaGetSymbolAddress((void**)&b1,  g_buf1);
    cudaGetSymbolAddress((void**)&w1q, g_w1qT);
    cudaGetSymbolAddress((void**)&w2q, g_w2qT);
    cudaGetSymbolAddress((void**)&w1k, g_w1kT);
    cudaGetSymbolAddress((void**)&w2k, g_w2kT);
    cudaGetSymbolAddress((void**)&whi, g_whi);
    cudaGetSymbolAddress((void**)&wlo, g_wlo);

    const int SM_Q1 = 36560, SM_K1 = 44832, SM_Q2 = 39024, SM_K2 = 70336;
    const int SM_T = 102400, SM_GOUT = 118000;

    cudaFuncSetAttribute((const void*)k_conv<256,261,5,31,40>,
                         cudaFuncAttributeMaxDynamicSharedMemorySize, SM_K2);
    cudaFuncSetAttribute((const void*)k_tlayer<40,1,false>,
                         cudaFuncAttributeMaxDynamicSharedMemorySize, SM_T);
    cudaFuncSetAttribute((const void*)k_tlayer<256,4,false>,
                         cudaFuncAttributeMaxDynamicSharedMemorySize, SM_T);
    cudaFuncSetAttribute((const void*)k_tlayer<256,4,true>,
                         cudaFuncAttributeMaxDynamicSharedMemorySize, SM_T);
    cudaFuncSetAttribute((const void*)k_gout,
                         cudaFuncAttributeMaxDynamicSharedMemorySize, SM_GOUT);

    k_dct<<<1, 400>>>();
    k_tr1<<<128, 256>>>(q_w1, w1q);
    k_tr1<<<128, 256>>>(k_w1, w1k);
    k_tr2<<<256, 256>>>(q_w2, w2q);
    k_tr2<<<256, 256>>>(k_w2, w2k);
    k_wpack<<<(13 * 65536 + 255) / 256, 256>>>(gin_w, blk_w);

    k_conv<66,69,6,5,13><<<B, 256, SM_Q1>>>(x, 3300, 40, w1q, q_b1, h1q);
    k_conv<256,261,5,1,40><<<B, 256, SM_Q2>>>(h1q, 1280, 0, w2q, q_b2, qv);
    k_conv<66,69,6,35,13><<<B, 256, SM_K1>>>(x, 3300, 0, w1k, k_b1, h1k);
    k_conv<256,261,5,31,40><<<B, 256, SM_K2>>>(h1k, 35*256, 0, w2k, k_b2, k2);

    k_att<<<B, 256>>>(qv, k2, att);
    k_gcninp<<<B, 264>>>(x, att, ginp);

    k_tlayer<40,1,false><<<B, 256, SM_T>>>(ginp, whi, wlo, gin_att, gin_b,
                                           bn_in_g, bn_in_b, nullptr, b0);
    for (int i = 0; i < 12; i += 2) {
        k_tlayer<256,4,false><<<B, 256, SM_T>>>(
            b0, whi + (size_t)(1 + i) * 65536, wlo + (size_t)(1 + i) * 65536,
            blk_att + (size_t)i * 4356, blk_b + (size_t)i * 256,
            blk_bn_g + (size_t)i * 16896, blk_bn_b + (size_t)i * 16896, nullptr, b1);
        k_tlayer<256,4,true><<<B, 256, SM_T>>>(
            b1, whi + (size_t)(2 + i) * 65536, wlo + (size_t)(2 + i) * 65536,
            blk_att + (size_t)(i + 1) * 4356, blk_b + (size_t)(i + 1) * 256,
            blk_bn_g + (size_t)(i + 1) * 16896, blk_bn_b + (size_t)(i + 1) * 16896,
            b0, b0);
    }
    k_gout<<<B, 256, SM_GOUT>>>(b0, ginp, gout_w, gout_att, gout_b, out);
}